// round 1
// baseline (speedup 1.0000x reference)
#include <cuda_runtime.h>
#include <math.h>

#define BATCH 64
#define CH 3
#define IMH 256
#define IMW 256
#define NB 256
#define NPIX (CH*IMH*IMW)   /* 196608 per batch */
#define TILE 32
#define RAD 5
#define KS 11
#define EXT 42              /* TILE + 2*RAD */

// Scratch (device globals: allocation-free per harness rules)
__device__ unsigned int d_hist[BATCH * NB * NB];   // 16 MB joint histograms
__device__ double d_ssim_sum[BATCH];
__device__ double d_mse_sum[BATCH];

// ---------------------------------------------------------------------------
// Kernel 1: zero scratch
// ---------------------------------------------------------------------------
__global__ void bsm_zero_kernel() {
    int idx = blockIdx.x * blockDim.x + threadIdx.x;
    int stride = gridDim.x * blockDim.x;
    const int total = BATCH * NB * NB;
    for (int i = idx; i < total; i += stride) d_hist[i] = 0u;
    if (idx < BATCH) {
        d_ssim_sum[idx] = 0.0;
        d_mse_sum[idx]  = 0.0;
    }
}

// ---------------------------------------------------------------------------
// Kernel 2: fused SSIM (separable 11x11 Gaussian) + MI histogram + MSE
// grid: (IMW/TILE, IMH/TILE, BATCH*CH), block: 256 threads
// ---------------------------------------------------------------------------
__global__ __launch_bounds__(256) void bsm_fused_kernel(
    const float* __restrict__ x,
    const float* __restrict__ y,
    const float* __restrict__ win)
{
    const int tid = threadIdx.x;
    const int img = blockIdx.z;        // b*CH + c
    const int b   = img / CH;
    const int tr  = blockIdx.y * TILE; // tile origin (row)
    const int tc  = blockIdx.x * TILE; // tile origin (col)

    __shared__ float sx[EXT * 44];
    __shared__ float sy[EXT * 44];
    __shared__ float hf0[EXT * TILE];
    __shared__ float hf1[EXT * TILE];
    __shared__ float hf2[EXT * TILE];
    __shared__ float hf3[EXT * TILE];
    __shared__ float hf4[EXT * TILE];
    __shared__ float g[16];
    __shared__ double sred[16];

    // Recover separable 1D gaussian: row sums of the 2D window (sum(g)=1).
    if (tid < KS) {
        float s = 0.f;
        #pragma unroll
        for (int j = 0; j < KS; j++) s += win[tid * KS + j];
        g[tid] = s;
    }

    const float* xi = x + (size_t)img * (IMH * IMW);
    const float* yi = y + (size_t)img * (IMH * IMW);

    // Load 42x42 halo tile with zero padding
    for (int i = tid; i < EXT * EXT; i += 256) {
        int r = i / EXT, c = i - r * EXT;
        int gr = tr + r - RAD, gc = tc + c - RAD;
        float xv = 0.f, yv = 0.f;
        if (gr >= 0 && gr < IMH && gc >= 0 && gc < IMW) {
            xv = xi[gr * IMW + gc];
            yv = yi[gr * IMW + gc];
        }
        sx[r * 44 + c] = xv;
        sy[r * 44 + c] = yv;
    }
    __syncthreads();

    // MI binning + MSE on the 32x32 interior (each element exactly once)
    float mse_loc = 0.f;
    {
        int c = tid & 31, r0 = tid >> 5;
        #pragma unroll
        for (int j = 0; j < 4; j++) {
            int r = r0 + j * 8;
            float xv = sx[(r + RAD) * 44 + c + RAD];
            float yv = sy[(r + RAD) * 44 + c + RAD];
            // exact op order of reference: xf=(x+1)*0.5; ix=trunc(xf*256)
            float xf = (xv + 1.0f) * 0.5f;
            float yf = (yv + 1.0f) * 0.5f;
            int ix = (int)(xf * 256.0f); ix = min(max(ix, 0), NB - 1);
            int iy = (int)(yf * 256.0f); iy = min(max(iy, 0), NB - 1);
            atomicAdd(&d_hist[b * (NB * NB) + ix * NB + iy], 1u);
            float d = (xv * 0.5f + 0.5f) - (yv * 0.5f + 0.5f);
            mse_loc += d * d;
        }
    }

    // Horizontal pass: 42 rows x 32 cols of 5 fields
    for (int i = tid; i < EXT * TILE; i += 256) {
        int r = i >> 5, c = i & 31;
        float a0 = 0.f, a1 = 0.f, a2 = 0.f, a3 = 0.f, a4 = 0.f;
        #pragma unroll
        for (int k = 0; k < KS; k++) {
            float w  = g[k];
            float xv = sx[r * 44 + c + k];
            float yv = sy[r * 44 + c + k];
            a0 += w * xv;
            a1 += w * yv;
            a2 += w * (xv * xv);
            a3 += w * (yv * yv);
            a4 += w * (xv * yv);
        }
        hf0[i] = a0; hf1[i] = a1; hf2[i] = a2; hf3[i] = a3; hf4[i] = a4;
    }
    __syncthreads();

    // Vertical pass + SSIM formula
    const float C1c = 0.01f * 0.01f;
    const float C2c = 0.03f * 0.03f;
    float ssim_loc = 0.f;
    {
        int c = tid & 31, r0 = tid >> 5;
        #pragma unroll
        for (int j = 0; j < 4; j++) {
            int r = r0 + j * 8;
            float mu1 = 0.f, mu2 = 0.f, m11 = 0.f, m22 = 0.f, m12 = 0.f;
            #pragma unroll
            for (int k = 0; k < KS; k++) {
                float w = g[k];
                int o = (r + k) * TILE + c;
                mu1 += w * hf0[o];
                mu2 += w * hf1[o];
                m11 += w * hf2[o];
                m22 += w * hf3[o];
                m12 += w * hf4[o];
            }
            float mu1s = mu1 * mu1;
            float mu2s = mu2 * mu2;
            float mu12 = mu1 * mu2;
            float s1  = m11 - mu1s;
            float s2  = m22 - mu2s;
            float s12 = m12 - mu12;
            float num = (2.f * mu12 + C1c) * (2.f * s12 + C2c);
            float den = (mu1s + mu2s + C1c) * (s1 + s2 + C2c);
            ssim_loc += num / den;
        }
    }

    // Block reduce ssim_loc + mse_loc, one double atomic each per block
    #pragma unroll
    for (int off = 16; off; off >>= 1) {
        ssim_loc += __shfl_down_sync(0xffffffffu, ssim_loc, off);
        mse_loc  += __shfl_down_sync(0xffffffffu, mse_loc,  off);
    }
    int lane = tid & 31, warp = tid >> 5;
    if (lane == 0) {
        sred[warp]     = (double)ssim_loc;
        sred[warp + 8] = (double)mse_loc;
    }
    __syncthreads();
    if (tid == 0) {
        double s = 0.0, m = 0.0;
        #pragma unroll
        for (int w = 0; w < 8; w++) { s += sred[w]; m += sred[w + 8]; }
        atomicAdd(&d_ssim_sum[b], s);
        atomicAdd(&d_mse_sum[b],  m);
    }
}

// ---------------------------------------------------------------------------
// Kernel 3: finalize — MI from histogram, normalize SSIM/PSNR, write out
// grid: BATCH blocks of 256 threads
// ---------------------------------------------------------------------------
__global__ __launch_bounds__(256) void bsm_finalize_kernel(float* __restrict__ out)
{
    const int b = blockIdx.x;
    const int t = threadIdx.x;
    const unsigned int* hb = &d_hist[b * NB * NB];
    const double invN = 1.0 / (double)NPIX;

    // Thread t owns histogram row t: px[t] and partial H(X,Y)
    double px = 0.0, hxy = 0.0;
    for (int j = 0; j < NB; j++) {
        unsigned int cnt = hb[t * NB + j];
        px += (double)cnt;
        if (cnt) {
            double p = (double)cnt * invN;
            hxy -= p * log2(p);
        }
    }
    // Thread t owns histogram column t: py[t]  (coalesced pass)
    double py = 0.0;
    for (int i = 0; i < NB; i++) py += (double)hb[i * NB + t];

    __shared__ double shx[256], shy[256], shxy[256];
    double pxn = px * invN, pyn = py * invN;
    shx[t]  = (pxn > 0.0) ? -pxn * log2(pxn) : 0.0;
    shy[t]  = (pyn > 0.0) ? -pyn * log2(pyn) : 0.0;
    shxy[t] = hxy;
    __syncthreads();
    for (int s = 128; s; s >>= 1) {
        if (t < s) {
            shx[t]  += shx[t + s];
            shy[t]  += shy[t + s];
            shxy[t] += shxy[t + s];
        }
        __syncthreads();
    }

    if (t == 0) {
        double hx = shx[0], hy = shy[0], hxyv = shxy[0];
        double mi = hx + hy - hxyv;               // == sum jp*log2(jp/(px*py))
        double norm = fmin(hx, hy);
        mi = (norm > 0.0) ? (mi / norm) : 0.0;
        mi = fmin(fmax(mi, 0.0), 1.0);

        double ssim = d_ssim_sum[b] * invN;

        double mse = d_mse_sum[b] * invN;
        double psnr = (mse == 0.0) ? 100.0 : (-10.0 * log10(mse));
        psnr /= 40.0;

        out[b * 3 + 0] = (float)mi;
        out[b * 3 + 1] = (float)ssim;
        out[b * 3 + 2] = (float)psnr;
    }
}

// ---------------------------------------------------------------------------
extern "C" void kernel_launch(void* const* d_in, const int* in_sizes, int n_in,
                              void* d_out, int out_size)
{
    const float* x   = (const float*)d_in[0];
    const float* y   = (const float*)d_in[1];
    const float* win = (const float*)d_in[2];
    float* out = (float*)d_out;

    bsm_zero_kernel<<<512, 256>>>();

    dim3 grid(IMW / TILE, IMH / TILE, BATCH * CH);
    bsm_fused_kernel<<<grid, 256>>>(x, y, win);

    bsm_finalize_kernel<<<BATCH, 256>>>(out);
}

// round 2
// speedup vs baseline: 1.0166x; 1.0166x over previous
#include <cuda_runtime.h>
#include <math.h>

#define BATCH 64
#define CH 3
#define IMH 256
#define IMW 256
#define NB 256
#define NPIX (CH*IMH*IMW)   /* 196608 per batch */
#define TILE 32
#define RAD 5
#define KS 11
#define EXT 42              /* TILE + 2*RAD */
#define SXS 43              /* odd stride for raw tiles: 8*43 % 32 != 0 -> no bank conflicts */
#define VFS 44              /* stride for intermediate fields (float4-aligned) */

// Scratch (device globals: allocation-free per harness rules)
__device__ unsigned int d_hist[BATCH * NB * NB];   // 16 MB joint histograms
__device__ double d_ssim_sum[BATCH];
__device__ double d_mse_sum[BATCH];

// ---------------------------------------------------------------------------
// Kernel 1: zero scratch (vectorized)
// ---------------------------------------------------------------------------
__global__ void bsm_zero_kernel() {
    int idx = blockIdx.x * blockDim.x + threadIdx.x;
    int stride = gridDim.x * blockDim.x;
    uint4* p = (uint4*)d_hist;
    const int total4 = (BATCH * NB * NB) / 4;
    for (int i = idx; i < total4; i += stride)
        p[i] = make_uint4(0u, 0u, 0u, 0u);
    if (idx < BATCH) {
        d_ssim_sum[idx] = 0.0;
        d_mse_sum[idx]  = 0.0;
    }
}

// ---------------------------------------------------------------------------
// Kernel 2: fused SSIM (separable 11x11, register-blocked) + MI hist + MSE
// grid: (IMW/TILE, IMH/TILE, BATCH*CH), block: 256 threads
// ---------------------------------------------------------------------------
__global__ __launch_bounds__(256) void bsm_fused_kernel(
    const float* __restrict__ x,
    const float* __restrict__ y,
    const float* __restrict__ win)
{
    const int tid = threadIdx.x;
    const int img = blockIdx.z;        // b*CH + c
    const int b   = img / CH;
    const int tr  = blockIdx.y * TILE; // tile origin (row)
    const int tc  = blockIdx.x * TILE; // tile origin (col)

    __shared__ float sx[EXT * SXS];
    __shared__ float sy[EXT * SXS];
    __shared__ float vf[5][TILE * VFS];   // vertically-convolved fields, col halo kept
    __shared__ float g1[16];
    __shared__ double sred[16];

    // Recover separable 1D gaussian: row sums of the 2D window (sum(g)=1).
    if (tid < KS) {
        float s = 0.f;
        #pragma unroll
        for (int j = 0; j < KS; j++) s += win[tid * KS + j];
        g1[tid] = s;
    }

    const float* xi = x + (size_t)img * (IMH * IMW);
    const float* yi = y + (size_t)img * (IMH * IMW);

    // ---- Phase A: load 42x42 halo tile with zero padding ----
    for (int i = tid; i < EXT * EXT; i += 256) {
        int r = i / EXT, c = i - r * EXT;
        int gr = tr + r - RAD, gc = tc + c - RAD;
        float xv = 0.f, yv = 0.f;
        if (gr >= 0 && gr < IMH && gc >= 0 && gc < IMW) {
            xv = xi[gr * IMW + gc];
            yv = yi[gr * IMW + gc];
        }
        sx[r * SXS + c] = xv;
        sy[r * SXS + c] = yv;
    }
    __syncthreads();

    // ---- MI binning + MSE on the 32x32 interior (reads only, no sync) ----
    float mse_loc = 0.f;
    {
        int c = tid & 31, r0 = tid >> 5;
        #pragma unroll
        for (int j = 0; j < 4; j++) {
            int r = r0 + j * 8;
            float xv = sx[(r + RAD) * SXS + c + RAD];
            float yv = sy[(r + RAD) * SXS + c + RAD];
            float xf = (xv + 1.0f) * 0.5f;
            float yf = (yv + 1.0f) * 0.5f;
            int ix = (int)(xf * 256.0f); ix = min(max(ix, 0), NB - 1);
            int iy = (int)(yf * 256.0f); iy = min(max(iy, 0), NB - 1);
            atomicAdd(&d_hist[b * (NB * NB) + ix * NB + iy], 1u);
            float d = (xv * 0.5f + 0.5f) - (yv * 0.5f + 0.5f);
            mse_loc += d * d;
        }
    }

    // ---- Phase B: VERTICAL pass on raw x,y -> 5 fields [32 rows x 42 cols] ----
    // Each work item: 4 output rows x 1 col. 8 row-groups x 42 cols = 336 items.
    #pragma unroll
    for (int it = 0; it < 2; it++) {
        int item = tid + it * 256;
        if (item < 8 * EXT) {
            int gr = item / EXT, c = item - gr * EXT;
            int r0 = gr * 4;
            float xin[14], yin[14];
            #pragma unroll
            for (int t = 0; t < 14; t++) {
                xin[t] = sx[(r0 + t) * SXS + c];
                yin[t] = sy[(r0 + t) * SXS + c];
            }
            float a0[4] = {0,0,0,0}, a1[4] = {0,0,0,0}, a2[4] = {0,0,0,0};
            float a3[4] = {0,0,0,0}, a4[4] = {0,0,0,0};
            #pragma unroll
            for (int k = 0; k < KS; k++) {
                float w = g1[k];
                #pragma unroll
                for (int j = 0; j < 4; j++) {
                    float xv = xin[j + k], yv = yin[j + k];
                    a0[j] += w * xv;
                    a1[j] += w * yv;
                    a2[j] += w * (xv * xv);
                    a3[j] += w * (yv * yv);
                    a4[j] += w * (xv * yv);
                }
            }
            #pragma unroll
            for (int j = 0; j < 4; j++) {
                int o = (r0 + j) * VFS + c;
                vf[0][o] = a0[j]; vf[1][o] = a1[j]; vf[2][o] = a2[j];
                vf[3][o] = a3[j]; vf[4][o] = a4[j];
            }
        }
    }
    __syncthreads();

    // ---- Phase C: HORIZONTAL pass, 1 row x 8 cols per thread (128 items) ----
    const float C1c = 0.01f * 0.01f;
    const float C2c = 0.03f * 0.03f;
    float ssim_loc = 0.f;
    if (tid < 128) {
        int r = tid >> 2, gg = tid & 3;
        int c0 = gg * 8;
        float acc[5][8];
        #pragma unroll
        for (int f = 0; f < 5; f++) {
            // load 18-float window for this field (float4-vectorized)
            float v[18];
            const float* base = &vf[f][r * VFS + c0];
            float4 q0 = *(const float4*)(base + 0);
            float4 q1 = *(const float4*)(base + 4);
            float4 q2 = *(const float4*)(base + 8);
            float4 q3 = *(const float4*)(base + 12);
            float2 q4 = *(const float2*)(base + 16);
            v[0]=q0.x; v[1]=q0.y; v[2]=q0.z; v[3]=q0.w;
            v[4]=q1.x; v[5]=q1.y; v[6]=q1.z; v[7]=q1.w;
            v[8]=q2.x; v[9]=q2.y; v[10]=q2.z; v[11]=q2.w;
            v[12]=q3.x; v[13]=q3.y; v[14]=q3.z; v[15]=q3.w;
            v[16]=q4.x; v[17]=q4.y;
            #pragma unroll
            for (int j = 0; j < 8; j++) acc[f][j] = 0.f;
            #pragma unroll
            for (int k = 0; k < KS; k++) {
                float w = g1[k];
                #pragma unroll
                for (int j = 0; j < 8; j++)
                    acc[f][j] += w * v[j + k];
            }
        }
        #pragma unroll
        for (int j = 0; j < 8; j++) {
            float mu1 = acc[0][j], mu2 = acc[1][j];
            float m11 = acc[2][j], m22 = acc[3][j], m12 = acc[4][j];
            float mu1s = mu1 * mu1;
            float mu2s = mu2 * mu2;
            float mu12 = mu1 * mu2;
            float s1  = m11 - mu1s;
            float s2  = m22 - mu2s;
            float s12 = m12 - mu12;
            float num = (2.f * mu12 + C1c) * (2.f * s12 + C2c);
            float den = (mu1s + mu2s + C1c) * (s1 + s2 + C2c);
            ssim_loc += num / den;
        }
    }

    // ---- Block reduce ssim_loc + mse_loc, one double atomic each per block ----
    #pragma unroll
    for (int off = 16; off; off >>= 1) {
        ssim_loc += __shfl_down_sync(0xffffffffu, ssim_loc, off);
        mse_loc  += __shfl_down_sync(0xffffffffu, mse_loc,  off);
    }
    int lane = tid & 31, warp = tid >> 5;
    if (lane == 0) {
        sred[warp]     = (double)ssim_loc;
        sred[warp + 8] = (double)mse_loc;
    }
    __syncthreads();
    if (tid == 0) {
        double s = 0.0, m = 0.0;
        #pragma unroll
        for (int w = 0; w < 8; w++) { s += sred[w]; m += sred[w + 8]; }
        atomicAdd(&d_ssim_sum[b], s);
        atomicAdd(&d_mse_sum[b],  m);
    }
}

// ---------------------------------------------------------------------------
// Kernel 3: finalize — MI from histogram, normalize SSIM/PSNR, write out
// ---------------------------------------------------------------------------
__global__ __launch_bounds__(256) void bsm_finalize_kernel(float* __restrict__ out)
{
    const int b = blockIdx.x;
    const int t = threadIdx.x;
    const unsigned int* hb = &d_hist[b * NB * NB];
    const double invN = 1.0 / (double)NPIX;

    // Thread t owns histogram row t: px[t] and partial H(X,Y)
    double px = 0.0, hxy = 0.0;
    for (int j = 0; j < NB; j++) {
        unsigned int cnt = hb[t * NB + j];
        px += (double)cnt;
        if (cnt) {
            double p = (double)cnt * invN;
            hxy -= p * log2(p);
        }
    }
    // Thread t owns histogram column t: py[t] (coalesced pass)
    double py = 0.0;
    for (int i = 0; i < NB; i++) py += (double)hb[i * NB + t];

    __shared__ double shx[256], shy[256], shxy[256];
    double pxn = px * invN, pyn = py * invN;
    shx[t]  = (pxn > 0.0) ? -pxn * log2(pxn) : 0.0;
    shy[t]  = (pyn > 0.0) ? -pyn * log2(pyn) : 0.0;
    shxy[t] = hxy;
    __syncthreads();
    for (int s = 128; s; s >>= 1) {
        if (t < s) {
            shx[t]  += shx[t + s];
            shy[t]  += shy[t + s];
            shxy[t] += shxy[t + s];
        }
        __syncthreads();
    }

    if (t == 0) {
        double hx = shx[0], hy = shy[0], hxyv = shxy[0];
        double mi = hx + hy - hxyv;
        double norm = fmin(hx, hy);
        mi = (norm > 0.0) ? (mi / norm) : 0.0;
        mi = fmin(fmax(mi, 0.0), 1.0);

        double ssim = d_ssim_sum[b] * invN;

        double mse = d_mse_sum[b] * invN;
        double psnr = (mse == 0.0) ? 100.0 : (-10.0 * log10(mse));
        psnr /= 40.0;

        out[b * 3 + 0] = (float)mi;
        out[b * 3 + 1] = (float)ssim;
        out[b * 3 + 2] = (float)psnr;
    }
}

// ---------------------------------------------------------------------------
extern "C" void kernel_launch(void* const* d_in, const int* in_sizes, int n_in,
                              void* d_out, int out_size)
{
    const float* x   = (const float*)d_in[0];
    const float* y   = (const float*)d_in[1];
    const float* win = (const float*)d_in[2];
    float* out = (float*)d_out;

    bsm_zero_kernel<<<2048, 256>>>();

    dim3 grid(IMW / TILE, IMH / TILE, BATCH * CH);
    bsm_fused_kernel<<<grid, 256>>>(x, y, win);

    bsm_finalize_kernel<<<BATCH, 256>>>(out);
}

// round 3
// speedup vs baseline: 3.5004x; 3.4433x over previous
#include <cuda_runtime.h>
#include <math.h>

#define BATCH 64
#define CH 3
#define NIMG (BATCH*CH)     /* 192 */
#define IMH 256
#define IMW 256
#define NB 256
#define NPIX (CH*IMH*IMW)   /* 196608 per batch */
#define RAD 5
#define KS 11

// Scratch (device globals: allocation-free per harness rules)
__device__ unsigned int d_hist[BATCH * NB * NB];        // 16 MB joint histograms
__device__ double d_ssim_sum[BATCH];
__device__ double d_mse_sum[BATCH];
__device__ float  d_field[5][NIMG * IMH * IMW];         // 251 MB staged h-conv fields

// ---------------------------------------------------------------------------
// Kernel 1: zero scratch (vectorized)
// ---------------------------------------------------------------------------
__global__ void bsm_zero_kernel() {
    int idx = blockIdx.x * blockDim.x + threadIdx.x;
    int stride = gridDim.x * blockDim.x;
    uint4* p = (uint4*)d_hist;
    const int total4 = (BATCH * NB * NB) / 4;
    for (int i = idx; i < total4; i += stride)
        p[i] = make_uint4(0u, 0u, 0u, 0u);
    if (idx < BATCH) {
        d_ssim_sum[idx] = 0.0;
        d_mse_sum[idx]  = 0.0;
    }
}

// ---------------------------------------------------------------------------
// Kernel 2 (K_H): horizontal 11-tap pass over full rows + MI hist + MSE.
// block = 256 threads handles 4 rows of one image. grid = (IMH/4, NIMG).
// ---------------------------------------------------------------------------
__global__ __launch_bounds__(256) void bsm_h_kernel(
    const float* __restrict__ x,
    const float* __restrict__ y,
    const float* __restrict__ win)
{
    const int tid = threadIdx.x;
    const int img = blockIdx.y;
    const int b   = img / CH;
    const int r0  = blockIdx.x * 4;

    __shared__ float rx[4][268];
    __shared__ float ry[4][268];
    __shared__ float g1[16];
    __shared__ double sred[8];

    // Separable 1D gaussian = row sums of the 2D window (sum(g)=1).
    if (tid < KS) {
        float s = 0.f;
        #pragma unroll
        for (int j = 0; j < KS; j++) s += win[tid * KS + j];
        g1[tid] = s;
    }
    // zero halos (image edge -> zero pad)
    if (tid < 5) {
        #pragma unroll
        for (int j = 0; j < 4; j++) {
            rx[j][tid] = 0.f; ry[j][tid] = 0.f;
            rx[j][IMW + 5 + tid] = 0.f; ry[j][IMW + 5 + tid] = 0.f;
        }
    }

    const size_t ibase = (size_t)img * (IMH * IMW);
    float mse_loc = 0.f;

    #pragma unroll
    for (int j = 0; j < 4; j++) {
        size_t base = ibase + (size_t)(r0 + j) * IMW;
        float xv = x[base + tid];
        float yv = y[base + tid];
        rx[j][5 + tid] = xv;
        ry[j][5 + tid] = yv;

        // MI binning (exact reference op order) + MSE
        float xf = (xv + 1.0f) * 0.5f;
        float yf = (yv + 1.0f) * 0.5f;
        int ix = (int)(xf * 256.0f); ix = min(max(ix, 0), NB - 1);
        int iy = (int)(yf * 256.0f); iy = min(max(iy, 0), NB - 1);
        atomicAdd(&d_hist[b * (NB * NB) + ix * NB + iy], 1u);
        float d = (xv * 0.5f + 0.5f) - (yv * 0.5f + 0.5f);
        mse_loc = fmaf(d, d, mse_loc);
    }
    __syncthreads();

    #pragma unroll
    for (int j = 0; j < 4; j++) {
        float a0 = 0.f, a1 = 0.f, a2 = 0.f, a3 = 0.f, a4 = 0.f;
        #pragma unroll
        for (int k = 0; k < KS; k++) {
            float w  = g1[k];
            float xs = rx[j][tid + k];
            float ys = ry[j][tid + k];
            a0 = fmaf(w, xs, a0);
            a1 = fmaf(w, ys, a1);
            a2 = fmaf(w, xs * xs, a2);
            a3 = fmaf(w, ys * ys, a3);
            a4 = fmaf(w, xs * ys, a4);
        }
        size_t o = ibase + (size_t)(r0 + j) * IMW + tid;
        d_field[0][o] = a0;
        d_field[1][o] = a1;
        d_field[2][o] = a2;
        d_field[3][o] = a3;
        d_field[4][o] = a4;
    }

    // block reduce mse -> one double atomic
    #pragma unroll
    for (int off = 16; off; off >>= 1)
        mse_loc += __shfl_down_sync(0xffffffffu, mse_loc, off);
    int lane = tid & 31, warp = tid >> 5;
    if (lane == 0) sred[warp] = (double)mse_loc;
    __syncthreads();
    if (tid == 0) {
        double m = 0.0;
        #pragma unroll
        for (int w = 0; w < 8; w++) m += sred[w];
        atomicAdd(&d_mse_sum[b], m);
    }
}

// ---------------------------------------------------------------------------
// Kernel 3 (K_V): vertical 11-tap pass + SSIM formula + reduction.
// block = 256 threads = 32 cols x 8 thread-rows; each thread-row -> 4 rows.
// grid = (IMW/32, IMH/32, NIMG). No tile smem; registers only.
// ---------------------------------------------------------------------------
__global__ __launch_bounds__(256) void bsm_v_kernel(const float* __restrict__ win)
{
    const int tid = threadIdx.x;
    const int img = blockIdx.z;
    const int b   = img / CH;

    __shared__ float g1[16];
    __shared__ double sred[8];

    if (tid < KS) {
        float s = 0.f;
        #pragma unroll
        for (int j = 0; j < KS; j++) s += win[tid * KS + j];
        g1[tid] = s;
    }
    __syncthreads();

    const int c   = tid & 31;
    const int col = blockIdx.x * 32 + c;
    const int r0  = blockIdx.y * 32 + (tid >> 5) * 4;
    const size_t ibase = (size_t)img * (IMH * IMW);

    float acc[5][4];
    #pragma unroll
    for (int f = 0; f < 5; f++) {
        float v[14];
        #pragma unroll
        for (int t = 0; t < 14; t++) {
            int rr = r0 + t - RAD;
            v[t] = (rr >= 0 && rr < IMH)
                 ? d_field[f][ibase + (size_t)rr * IMW + col] : 0.f;
        }
        #pragma unroll
        for (int j = 0; j < 4; j++) acc[f][j] = 0.f;
        #pragma unroll
        for (int k = 0; k < KS; k++) {
            float w = g1[k];
            #pragma unroll
            for (int j = 0; j < 4; j++)
                acc[f][j] = fmaf(w, v[j + k], acc[f][j]);
        }
    }

    const float C1c = 0.01f * 0.01f;
    const float C2c = 0.03f * 0.03f;
    float ssim_loc = 0.f;
    #pragma unroll
    for (int j = 0; j < 4; j++) {
        float mu1 = acc[0][j], mu2 = acc[1][j];
        float m11 = acc[2][j], m22 = acc[3][j], m12 = acc[4][j];
        float mu1s = mu1 * mu1;
        float mu2s = mu2 * mu2;
        float mu12 = mu1 * mu2;
        float s1  = m11 - mu1s;
        float s2  = m22 - mu2s;
        float s12 = m12 - mu12;
        float num = (2.f * mu12 + C1c) * (2.f * s12 + C2c);
        float den = (mu1s + mu2s + C1c) * (s1 + s2 + C2c);
        ssim_loc += num / den;
    }

    #pragma unroll
    for (int off = 16; off; off >>= 1)
        ssim_loc += __shfl_down_sync(0xffffffffu, ssim_loc, off);
    int lane = tid & 31, warp = tid >> 5;
    if (lane == 0) sred[warp] = (double)ssim_loc;
    __syncthreads();
    if (tid == 0) {
        double s = 0.0;
        #pragma unroll
        for (int w = 0; w < 8; w++) s += sred[w];
        atomicAdd(&d_ssim_sum[b], s);
    }
}

// ---------------------------------------------------------------------------
// Kernel 4: finalize — MI from histogram (float log2f), SSIM/PSNR, write out
// ---------------------------------------------------------------------------
__global__ __launch_bounds__(256) void bsm_finalize_kernel(float* __restrict__ out)
{
    const int b = blockIdx.x;
    const int t = threadIdx.x;
    const unsigned int* hb = &d_hist[b * NB * NB];
    const float invNf = 1.0f / (float)NPIX;
    const double invN = 1.0 / (double)NPIX;

    // Thread t owns histogram row t: px[t] and partial H(X,Y)
    unsigned int px = 0;
    float hxy = 0.f;
    for (int j = 0; j < NB; j++) {
        unsigned int cnt = hb[t * NB + j];
        px += cnt;
        if (cnt) {
            float p = (float)cnt * invNf;
            hxy -= p * log2f(p);
        }
    }
    // Thread t owns histogram column t: py[t] (coalesced pass)
    unsigned int py = 0;
    for (int i = 0; i < NB; i++) py += hb[i * NB + t];

    __shared__ double shx[256], shy[256], shxy[256];
    float pxn = (float)px * invNf, pyn = (float)py * invNf;
    shx[t]  = (pxn > 0.f) ? (double)(-pxn * log2f(pxn)) : 0.0;
    shy[t]  = (pyn > 0.f) ? (double)(-pyn * log2f(pyn)) : 0.0;
    shxy[t] = (double)hxy;
    __syncthreads();
    for (int s = 128; s; s >>= 1) {
        if (t < s) {
            shx[t]  += shx[t + s];
            shy[t]  += shy[t + s];
            shxy[t] += shxy[t + s];
        }
        __syncthreads();
    }

    if (t == 0) {
        double hx = shx[0], hy = shy[0], hxyv = shxy[0];
        double mi = hx + hy - hxyv;
        double norm = fmin(hx, hy);
        mi = (norm > 0.0) ? (mi / norm) : 0.0;
        mi = fmin(fmax(mi, 0.0), 1.0);

        double ssim = d_ssim_sum[b] * invN;

        double mse = d_mse_sum[b] * invN;
        double psnr = (mse == 0.0) ? 100.0 : (-10.0 * log10(mse));
        psnr /= 40.0;

        out[b * 3 + 0] = (float)mi;
        out[b * 3 + 1] = (float)ssim;
        out[b * 3 + 2] = (float)psnr;
    }
}

// ---------------------------------------------------------------------------
extern "C" void kernel_launch(void* const* d_in, const int* in_sizes, int n_in,
                              void* d_out, int out_size)
{
    const float* x   = (const float*)d_in[0];
    const float* y   = (const float*)d_in[1];
    const float* win = (const float*)d_in[2];
    float* out = (float*)d_out;

    bsm_zero_kernel<<<2048, 256>>>();

    dim3 gh(IMH / 4, NIMG);
    bsm_h_kernel<<<gh, 256>>>(x, y, win);

    dim3 gv(IMW / 32, IMH / 32, NIMG);
    bsm_v_kernel<<<gv, 256>>>(win);

    bsm_finalize_kernel<<<BATCH, 256>>>(out);
}

// round 5
// speedup vs baseline: 4.6261x; 1.3216x over previous
#include <cuda_runtime.h>
#include <cuda_fp16.h>
#include <math.h>

#define BATCH 64
#define CH 3
#define NIMG (BATCH*CH)     /* 192 */
#define IMH 256
#define IMW 256
#define NB 256
#define NPIX (CH*IMH*IMW)   /* 196608 per batch */
#define RAD 5
#define KS 11

// Scratch (device globals: allocation-free per harness rules)
__device__ unsigned int d_hist[BATCH * NB * NB];        // 16 MB joint histograms
__device__ unsigned int d_py[BATCH * NB];               // marginal-y partial sums
__device__ double d_hx[BATCH];
__device__ double d_hxy[BATCH];
__device__ double d_ssim_sum[BATCH];
__device__ double d_mse_sum[BATCH];
// fp16-staged horizontally-convolved fields (125 MB total)
__device__ __half2 d_f01[NIMG * IMH * IMW];             // (conv x, conv y)
__device__ __half2 d_f23[NIMG * IMH * IMW];             // (conv x2, conv y2)
__device__ __half  d_f4 [NIMG * IMH * IMW];             // conv xy

// ---------------------------------------------------------------------------
// Kernel 1: zero scratch (vectorized)
// ---------------------------------------------------------------------------
__global__ void bsm_zero_kernel() {
    int idx = blockIdx.x * blockDim.x + threadIdx.x;
    int stride = gridDim.x * blockDim.x;
    uint4* p = (uint4*)d_hist;
    const int total4 = (BATCH * NB * NB) / 4;
    for (int i = idx; i < total4; i += stride)
        p[i] = make_uint4(0u, 0u, 0u, 0u);
    if (idx < BATCH * NB) d_py[idx] = 0u;
    if (idx < BATCH) {
        d_hx[idx] = 0.0;
        d_hxy[idx] = 0.0;
        d_ssim_sum[idx] = 0.0;
        d_mse_sum[idx]  = 0.0;
    }
}

// ---------------------------------------------------------------------------
// Kernel 2 (K_H): horizontal 11-tap pass over full rows + MI hist + MSE.
// block = 256 threads handles 4 rows of one image. grid = (IMH/4, NIMG).
// ---------------------------------------------------------------------------
__global__ __launch_bounds__(256) void bsm_h_kernel(
    const float* __restrict__ x,
    const float* __restrict__ y,
    const float* __restrict__ win)
{
    const int tid = threadIdx.x;
    const int img = blockIdx.y;
    const int b   = img / CH;
    const int r0  = blockIdx.x * 4;

    __shared__ float rx[4][268];
    __shared__ float ry[4][268];
    __shared__ float g1[16];
    __shared__ double sred[8];

    // Separable 1D gaussian = row sums of the 2D window (sum(g)=1).
    if (tid < KS) {
        float s = 0.f;
        #pragma unroll
        for (int j = 0; j < KS; j++) s += win[tid * KS + j];
        g1[tid] = s;
    }
    // zero halos (image edge -> zero pad)
    if (tid < 5) {
        #pragma unroll
        for (int j = 0; j < 4; j++) {
            rx[j][tid] = 0.f; ry[j][tid] = 0.f;
            rx[j][IMW + 5 + tid] = 0.f; ry[j][IMW + 5 + tid] = 0.f;
        }
    }

    const size_t ibase = (size_t)img * (IMH * IMW);
    float mse_loc = 0.f;

    #pragma unroll
    for (int j = 0; j < 4; j++) {
        size_t base = ibase + (size_t)(r0 + j) * IMW;
        float xv = x[base + tid];
        float yv = y[base + tid];
        rx[j][5 + tid] = xv;
        ry[j][5 + tid] = yv;

        // MI binning (exact reference op order) + MSE
        float xf = (xv + 1.0f) * 0.5f;
        float yf = (yv + 1.0f) * 0.5f;
        int ix = (int)(xf * 256.0f); ix = min(max(ix, 0), NB - 1);
        int iy = (int)(yf * 256.0f); iy = min(max(iy, 0), NB - 1);
        atomicAdd(&d_hist[b * (NB * NB) + ix * NB + iy], 1u);
        float d = (xv * 0.5f + 0.5f) - (yv * 0.5f + 0.5f);
        mse_loc = fmaf(d, d, mse_loc);
    }
    __syncthreads();

    #pragma unroll
    for (int j = 0; j < 4; j++) {
        float a0 = 0.f, a1 = 0.f, a2 = 0.f, a3 = 0.f, a4 = 0.f;
        #pragma unroll
        for (int k = 0; k < KS; k++) {
            float w  = g1[k];
            float xs = rx[j][tid + k];
            float ys = ry[j][tid + k];
            a0 = fmaf(w, xs, a0);
            a1 = fmaf(w, ys, a1);
            a2 = fmaf(w, xs * xs, a2);
            a3 = fmaf(w, ys * ys, a3);
            a4 = fmaf(w, xs * ys, a4);
        }
        size_t o = ibase + (size_t)(r0 + j) * IMW + tid;
        d_f01[o] = __floats2half2_rn(a0, a1);
        d_f23[o] = __floats2half2_rn(a2, a3);
        d_f4[o]  = __float2half_rn(a4);
    }

    // block reduce mse -> one double atomic
    #pragma unroll
    for (int off = 16; off; off >>= 1)
        mse_loc += __shfl_down_sync(0xffffffffu, mse_loc, off);
    int lane = tid & 31, warp = tid >> 5;
    if (lane == 0) sred[warp] = (double)mse_loc;
    __syncthreads();
    if (tid == 0) {
        double m = 0.0;
        #pragma unroll
        for (int w = 0; w < 8; w++) m += sred[w];
        atomicAdd(&d_mse_sum[b], m);
    }
}

// ---------------------------------------------------------------------------
// Kernel 3 (K_V): vertical 11-tap pass + SSIM formula + reduction.
// block = 256 threads = 32 cols x 8 row-groups; each row-group -> 4 rows.
// grid = (IMW/32, IMH/32, NIMG). Registers only, fp16 field loads.
// ---------------------------------------------------------------------------
__global__ __launch_bounds__(256) void bsm_v_kernel(const float* __restrict__ win)
{
    const int tid = threadIdx.x;
    const int img = blockIdx.z;
    const int b   = img / CH;

    __shared__ float g1[16];
    __shared__ double sred[8];

    if (tid < KS) {
        float s = 0.f;
        #pragma unroll
        for (int j = 0; j < KS; j++) s += win[tid * KS + j];
        g1[tid] = s;
    }
    __syncthreads();

    const int c   = tid & 31;
    const int col = blockIdx.x * 32 + c;
    const int r0  = blockIdx.y * 32 + (tid >> 5) * 4;
    const size_t ibase = (size_t)img * (IMH * IMW);

    float mu1[4], mu2[4], m11[4], m22[4], m12[4];

    // fields 0,1 (mu1, mu2)
    {
        float2 v[14];
        #pragma unroll
        for (int t = 0; t < 14; t++) {
            int rr = r0 + t - RAD;
            v[t] = (rr >= 0 && rr < IMH)
                 ? __half22float2(d_f01[ibase + (size_t)rr * IMW + col])
                 : make_float2(0.f, 0.f);
        }
        #pragma unroll
        for (int j = 0; j < 4; j++) { mu1[j] = 0.f; mu2[j] = 0.f; }
        #pragma unroll
        for (int k = 0; k < KS; k++) {
            float w = g1[k];
            #pragma unroll
            for (int j = 0; j < 4; j++) {
                mu1[j] = fmaf(w, v[j + k].x, mu1[j]);
                mu2[j] = fmaf(w, v[j + k].y, mu2[j]);
            }
        }
    }
    // fields 2,3 (m11, m22)
    {
        float2 v[14];
        #pragma unroll
        for (int t = 0; t < 14; t++) {
            int rr = r0 + t - RAD;
            v[t] = (rr >= 0 && rr < IMH)
                 ? __half22float2(d_f23[ibase + (size_t)rr * IMW + col])
                 : make_float2(0.f, 0.f);
        }
        #pragma unroll
        for (int j = 0; j < 4; j++) { m11[j] = 0.f; m22[j] = 0.f; }
        #pragma unroll
        for (int k = 0; k < KS; k++) {
            float w = g1[k];
            #pragma unroll
            for (int j = 0; j < 4; j++) {
                m11[j] = fmaf(w, v[j + k].x, m11[j]);
                m22[j] = fmaf(w, v[j + k].y, m22[j]);
            }
        }
    }
    // field 4 (m12)
    {
        float v[14];
        #pragma unroll
        for (int t = 0; t < 14; t++) {
            int rr = r0 + t - RAD;
            v[t] = (rr >= 0 && rr < IMH)
                 ? __half2float(d_f4[ibase + (size_t)rr * IMW + col]) : 0.f;
        }
        #pragma unroll
        for (int j = 0; j < 4; j++) m12[j] = 0.f;
        #pragma unroll
        for (int k = 0; k < KS; k++) {
            float w = g1[k];
            #pragma unroll
            for (int j = 0; j < 4; j++)
                m12[j] = fmaf(w, v[j + k], m12[j]);
        }
    }

    const float C1c = 0.01f * 0.01f;
    const float C2c = 0.03f * 0.03f;
    float ssim_loc = 0.f;
    #pragma unroll
    for (int j = 0; j < 4; j++) {
        float mu1s = mu1[j] * mu1[j];
        float mu2s = mu2[j] * mu2[j];
        float mu12 = mu1[j] * mu2[j];
        float s1  = m11[j] - mu1s;
        float s2  = m22[j] - mu2s;
        float s12 = m12[j] - mu12;
        float num = (2.f * mu12 + C1c) * (2.f * s12 + C2c);
        float den = (mu1s + mu2s + C1c) * (s1 + s2 + C2c);
        ssim_loc += num / den;
    }

    #pragma unroll
    for (int off = 16; off; off >>= 1)
        ssim_loc += __shfl_down_sync(0xffffffffu, ssim_loc, off);
    int lane = tid & 31, warp = tid >> 5;
    if (lane == 0) sred[warp] = (double)ssim_loc;
    __syncthreads();
    if (tid == 0) {
        double s = 0.0;
        #pragma unroll
        for (int w = 0; w < 8; w++) s += sred[w];
        atomicAdd(&d_ssim_sum[b], s);
    }
}

// ---------------------------------------------------------------------------
// Kernel 4a: histogram scan — coalesced uint4 reads.
// grid = (4 chunks, 64 batches), block = 256 (8 warps, warp -> 8 rows).
// Produces: d_hx[b], d_hxy[b] (double atomics), d_py[b][col] (uint atomics).
// ---------------------------------------------------------------------------
__global__ __launch_bounds__(256) void bsm_fin_a_kernel()
{
    const int b     = blockIdx.y;
    const int chunk = blockIdx.x;
    const int tid   = threadIdx.x;
    const int lane  = tid & 31;
    const int warp  = tid >> 5;

    __shared__ unsigned int spy[NB];
    __shared__ double sredA[8], sredB[8];

    spy[tid] = 0u;
    __syncthreads();

    const uint4* hb4 = (const uint4*)&d_hist[b * NB * NB];
    const float invNf = 1.0f / (float)NPIX;

    double hxy_loc = 0.0;   // accumulates H(X,Y) contributions (positive)
    double hx_loc  = 0.0;   // accumulates H(X) contributions (positive)

    // warp handles 8 consecutive rows
    #pragma unroll
    for (int rr = 0; rr < 8; rr++) {
        int row = chunk * 64 + warp * 8 + rr;
        // row = 256 uints = 64 uint4; lane covers 2 uint4
        uint4 q0 = hb4[row * 64 + lane];
        uint4 q1 = hb4[row * 64 + 32 + lane];
        unsigned int cs[8] = {q0.x, q0.y, q0.z, q0.w, q1.x, q1.y, q1.z, q1.w};

        unsigned int px_part = 0;
        float h_part = 0.f;      // Σ -p*log2(p) over this lane's 8 bins
        #pragma unroll
        for (int k = 0; k < 8; k++) {
            unsigned int cnt = cs[k];
            px_part += cnt;
            if (cnt) {
                float p = (float)cnt * invNf;
                h_part -= p * log2f(p);
                int colk = (k < 4) ? (lane * 4 + k) : (128 + lane * 4 + (k - 4));
                atomicAdd(&spy[colk], cnt);
            }
        }
        hxy_loc += (double)h_part;

        // warp-reduce px_part -> row marginal entropy on lane 0
        #pragma unroll
        for (int off = 16; off; off >>= 1)
            px_part += __shfl_down_sync(0xffffffffu, px_part, off);
        if (lane == 0 && px_part) {
            float pxn = (float)px_part * invNf;
            hx_loc -= (double)(pxn * log2f(pxn));
        }
    }

    // block-reduce hxy_loc (all lanes) and hx_loc (lane0s only)
    #pragma unroll
    for (int off = 16; off; off >>= 1)
        hxy_loc += __shfl_down_sync(0xffffffffu, hxy_loc, off);
    if (lane == 0) { sredA[warp] = hxy_loc; sredB[warp] = hx_loc; }
    __syncthreads();
    if (tid == 0) {
        double a = 0.0, bb = 0.0;
        #pragma unroll
        for (int w = 0; w < 8; w++) { a += sredA[w]; bb += sredB[w]; }
        atomicAdd(&d_hxy[b], a);
        atomicAdd(&d_hx[b],  bb);
    }
    __syncthreads();
    if (spy[tid]) atomicAdd(&d_py[b * NB + tid], spy[tid]);
}

// ---------------------------------------------------------------------------
// Kernel 4b: combine — H(Y) from d_py, final MI/SSIM/PSNR, write out.
// ---------------------------------------------------------------------------
__global__ __launch_bounds__(256) void bsm_fin_b_kernel(float* __restrict__ out)
{
    const int b = blockIdx.x;
    const int t = threadIdx.x;
    const float invNf = 1.0f / (float)NPIX;
    const double invN = 1.0 / (double)NPIX;

    __shared__ double shy[256];
    unsigned int py = d_py[b * NB + t];
    float pyn = (float)py * invNf;
    shy[t] = (py > 0) ? (double)(-pyn * log2f(pyn)) : 0.0;
    __syncthreads();
    for (int s = 128; s; s >>= 1) {
        if (t < s) shy[t] += shy[t + s];
        __syncthreads();
    }

    if (t == 0) {
        double hx = d_hx[b], hy = shy[0], hxyv = d_hxy[b];
        double mi = hx + hy - hxyv;
        double norm = fmin(hx, hy);
        mi = (norm > 0.0) ? (mi / norm) : 0.0;
        mi = fmin(fmax(mi, 0.0), 1.0);

        double ssim = d_ssim_sum[b] * invN;

        double mse = d_mse_sum[b] * invN;
        double psnr = (mse == 0.0) ? 100.0 : (-10.0 * log10(mse));
        psnr /= 40.0;

        out[b * 3 + 0] = (float)mi;
        out[b * 3 + 1] = (float)ssim;
        out[b * 3 + 2] = (float)psnr;
    }
}

// ---------------------------------------------------------------------------
extern "C" void kernel_launch(void* const* d_in, const int* in_sizes, int n_in,
                              void* d_out, int out_size)
{
    const float* x   = (const float*)d_in[0];
    const float* y   = (const float*)d_in[1];
    const float* win = (const float*)d_in[2];
    float* out = (float*)d_out;

    bsm_zero_kernel<<<2048, 256>>>();

    dim3 gh(IMH / 4, NIMG);
    bsm_h_kernel<<<gh, 256>>>(x, y, win);

    dim3 gv(IMW / 32, IMH / 32, NIMG);
    bsm_v_kernel<<<gv, 256>>>(win);

    dim3 gf(4, BATCH);
    bsm_fin_a_kernel<<<gf, 256>>>();
    bsm_fin_b_kernel<<<BATCH, 256>>>(out);
}